// round 15
// baseline (speedup 1.0000x reference)
#include <cuda_runtime.h>

#define MAX_B 16384
#define CHUNK 512   // items per CTA (16 slots x 32)

// Per-segment partial sums [B,64] and flush counters. Zero at entry:
// static init on first call; the electing winner re-zeroes after consuming.
__device__ float    g_scratch[MAX_B * 64];
__device__ unsigned g_cnt[MAX_B];

__global__ __launch_bounds__(256)
void svdpp_fused(const int* __restrict__ user_ids,
                 const int* __restrict__ item_ids,
                 const int* __restrict__ offsets,
                 const int* __restrict__ flat_implicit,
                 const float4* __restrict__ user_emb4,
                 const float4* __restrict__ item_emb4,
                 const float4* __restrict__ imp_emb4,
                 const float* __restrict__ user_bias,
                 const float* __restrict__ item_bias,
                 const float* __restrict__ global_bias,
                 float* __restrict__ out,
                 int B, int N) {
    const int t    = threadIdx.x;
    const int lane = t & 15;            // float4 chunk of the 64-dim row
    const int slot = t >> 4;            // 0..15
    const unsigned gmask = 0xFFFFu << (t & 16);   // this 16-lane group's mask

    // ---- empty rows (len==0): handled here, overlapped with the gather ----
    {
        const int g = blockIdx.x * 256 + t;
        if (g < B) {
            const int s0 = __ldg(&offsets[g]);
            const int s1 = (g + 1 < B) ? __ldg(&offsets[g + 1]) : N;
            if (s1 == s0) {
                const int u  = __ldg(&user_ids[g]);
                const int it = __ldg(&item_ids[g]);
                float dot = 0.f;
                #pragma unroll 4
                for (int c = 0; c < 16; ++c) {
                    const float4 a = __ldg(&user_emb4[(size_t)u  * 16 + c]);
                    const float4 v = __ldg(&item_emb4[(size_t)it * 16 + c]);
                    dot += a.x * v.x + a.y * v.y + a.z * v.z + a.w * v.w;
                }
                out[g] = dot + __ldg(&user_bias[u]) + __ldg(&item_bias[it])
                             + __ldg(&global_bias[0]);
            }
        }
    }

    int j = blockIdx.x * CHUNK + slot * 32;     // 32-aligned run start
    if (j >= N) return;                          // uniform per 16-lane group
    const int run_end = min(j + 32, N);

    // Binary search: seg = last b with offsets[b] <= j.
    int lo = 0, hi = B;
    while (lo < hi) {
        const int mid = (lo + hi) >> 1;
        if (__ldg(&offsets[mid]) <= j) lo = mid + 1; else hi = mid;
    }
    int seg = lo - 1;

    float4 acc = make_float4(0.f, 0.f, 0.f, 0.f);

    for (;;) {
        const int nb   = (seg + 1 < B) ? __ldg(&offsets[seg + 1]) : N;
        const int stop = min(run_end, nb);

        // Hot loop: 4 independent LDG.128 in flight per thread.
        for (; j + 3 < stop; j += 4) {
            const int i0 = __ldg(&flat_implicit[j]);
            const int i1 = __ldg(&flat_implicit[j + 1]);
            const int i2 = __ldg(&flat_implicit[j + 2]);
            const int i3 = __ldg(&flat_implicit[j + 3]);
            const float4 a0 = __ldg(&imp_emb4[(size_t)i0 * 16 + lane]);
            const float4 a1 = __ldg(&imp_emb4[(size_t)i1 * 16 + lane]);
            const float4 a2 = __ldg(&imp_emb4[(size_t)i2 * 16 + lane]);
            const float4 a3 = __ldg(&imp_emb4[(size_t)i3 * 16 + lane]);
            acc.x += (a0.x + a1.x) + (a2.x + a3.x);
            acc.y += (a0.y + a1.y) + (a2.y + a3.y);
            acc.z += (a0.z + a1.z) + (a2.z + a3.z);
            acc.w += (a0.w + a1.w) + (a2.w + a3.w);
        }
        for (; j < stop; ++j) {
            const float4 a = __ldg(&imp_emb4[(size_t)__ldg(&flat_implicit[j]) * 16 + lane]);
            acc.x += a.x; acc.y += a.y; acc.z += a.z; acc.w += a.w;
        }

        // ---- flush this (run, seg) partial ----
        float* dst = g_scratch + (size_t)seg * 64 + lane * 4;
        atomicAdd(dst + 0, acc.x);
        atomicAdd(dst + 1, acc.y);
        atomicAdd(dst + 2, acc.z);
        atomicAdd(dst + 3, acc.w);

        __syncwarp(gmask);

        int win = 0;
        int s0w = 0;
        if (lane == 0) {
            __threadfence();                         // order flush before count
            const unsigned old = atomicAdd(&g_cnt[seg], 1u);
            s0w = __ldg(&offsets[seg]);
            const unsigned runs =
                (unsigned)(((nb - 1) >> 5) - (s0w >> 5) + 1);
            win = (old + 1u == runs);
        }
        win = __shfl_sync(gmask, win, 0, 16);

        if (win) {
            // All prior flushes visible (each fenced before its count bump).
            float4* srow = reinterpret_cast<float4*>(g_scratch) + (size_t)seg * 16 + lane;
            const float4 sum = __ldcg(srow);
            __stcg(srow, make_float4(0.f, 0.f, 0.f, 0.f));   // restore invariant
            if (lane == 0) g_cnt[seg] = 0u;

            const int s0  = __shfl_sync(gmask, s0w, 0, 16);
            const int len = nb - s0;                 // > 0 here
            const float invnorm = rsqrtf((float)len);

            const int u  = __ldg(&user_ids[seg]);
            const int it = __ldg(&item_ids[seg]);
            const float4 u4 = __ldg(&user_emb4[(size_t)u  * 16 + lane]);
            const float4 i4 = __ldg(&item_emb4[(size_t)it * 16 + lane]);

            float dot = (u4.x + sum.x * invnorm) * i4.x
                      + (u4.y + sum.y * invnorm) * i4.y
                      + (u4.z + sum.z * invnorm) * i4.z
                      + (u4.w + sum.w * invnorm) * i4.w;

            #pragma unroll
            for (int off = 8; off > 0; off >>= 1)
                dot += __shfl_down_sync(gmask, dot, off, 16);

            if (lane == 0)
                out[seg] = dot + __ldg(&user_bias[u]) + __ldg(&item_bias[it])
                               + __ldg(&global_bias[0]);
        }

        if (stop >= run_end) break;
        acc = make_float4(0.f, 0.f, 0.f, 0.f);
        seg++;
        while (seg + 1 < B && __ldg(&offsets[seg + 1]) <= j) seg++;  // skip empties
    }
}

extern "C" void kernel_launch(void* const* d_in, const int* in_sizes, int n_in,
                              void* d_out, int out_size) {
    const int*    user_ids      = (const int*)d_in[0];
    const int*    item_ids      = (const int*)d_in[1];
    const int*    offsets       = (const int*)d_in[2];
    const int*    flat_implicit = (const int*)d_in[3];
    const float4* user_emb4     = (const float4*)d_in[4];
    const float4* item_emb4     = (const float4*)d_in[5];
    const float4* imp_emb4      = (const float4*)d_in[6];
    const float*  user_bias     = (const float*)d_in[7];
    const float*  item_bias     = (const float*)d_in[8];
    const float*  global_bias   = (const float*)d_in[9];
    float*        out           = (float*)d_out;

    const int B = in_sizes[0];          // 16384
    const int N = in_sizes[3];          // 819200

    svdpp_fused<<<(N + CHUNK - 1) / CHUNK, 256>>>(
        user_ids, item_ids, offsets, flat_implicit,
        user_emb4, item_emb4, imp_emb4,
        user_bias, item_bias, global_bias, out, B, N);
}

// round 16
// speedup vs baseline: 1.5639x; 1.5639x over previous
#include <cuda_runtime.h>

// Warp-per-row. Per 32 items: ONE coalesced index load, then 16 independent
// warp-wide row loads (lanes 0-15 = even item, 16-31 = odd item; each half
// reads 16B chunks of a 256B row). Indices distributed via variable-src shfl.

__global__ __launch_bounds__(128)
void svdpp_kernel(const int* __restrict__ user_ids,
                  const int* __restrict__ item_ids,
                  const int* __restrict__ offsets,
                  const int* __restrict__ flat_implicit,
                  const float4* __restrict__ user_emb4,
                  const float4* __restrict__ item_emb4,
                  const float4* __restrict__ imp_emb4,
                  const float* __restrict__ user_bias,
                  const float* __restrict__ item_bias,
                  const float* __restrict__ global_bias,
                  float* __restrict__ out,
                  int B, int N) {
    const int lane = threadIdx.x & 31;
    const int half = lane >> 4;          // 0: even items, 1: odd items
    const int c    = lane & 15;          // float4 chunk of the 256B row
    const int b    = (blockIdx.x << 2) + (threadIdx.x >> 5);
    if (b >= B) return;

    const int start = __ldg(&offsets[b]);
    const int end   = (b + 1 < B) ? __ldg(&offsets[b + 1]) : N;
    const int len   = end - start;

    // Epilogue operands issued early; latency hides under the gather.
    const int u  = __ldg(&user_ids[b]);
    const int it = __ldg(&item_ids[b]);
    const float4 u4 = __ldg(&user_emb4[(size_t)u * 16 + c]);
    const float4 i4 = __ldg(&item_emb4[(size_t)it * 16 + c]);
    const float  ub = __ldg(&user_bias[u]);
    const float  ib = __ldg(&item_bias[it]);
    const float  gb = __ldg(&global_bias[0]);

    float4 acc = make_float4(0.f, 0.f, 0.f, 0.f);

    int j = start;
    // Full 32-item blocks: 1 index load + 16 independent row loads.
    for (; j + 32 <= end; j += 32) {
        const int idx = __ldg(&flat_implicit[j + lane]);
        #pragma unroll
        for (int r = 0; r < 16; ++r) {
            const int row = __shfl_sync(0xffffffffu, idx, 2 * r + half);
            const float4 a = __ldg(&imp_emb4[(size_t)row * 16 + c]);
            acc.x += a.x; acc.y += a.y; acc.z += a.z; acc.w += a.w;
        }
    }
    // Tail (< 32 items).
    const int rem = end - j;
    if (rem > 0) {
        const int idx = (lane < rem) ? __ldg(&flat_implicit[j + lane]) : 0;
        for (int r = 0; 2 * r < rem; ++r) {          // warp-uniform bound
            const int item = 2 * r + half;
            const int row  = __shfl_sync(0xffffffffu, idx, item);
            if (item < rem) {
                const float4 a = __ldg(&imp_emb4[(size_t)row * 16 + c]);
                acc.x += a.x; acc.y += a.y; acc.z += a.z; acc.w += a.w;
            }
        }
    }

    // Fold odd-item half onto even-item half.
    acc.x += __shfl_xor_sync(0xffffffffu, acc.x, 16);
    acc.y += __shfl_xor_sync(0xffffffffu, acc.y, 16);
    acc.z += __shfl_xor_sync(0xffffffffu, acc.z, 16);
    acc.w += __shfl_xor_sync(0xffffffffu, acc.w, 16);

    const float invnorm = (len > 0) ? rsqrtf((float)len) : 1.0f;

    float dot = (u4.x + acc.x * invnorm) * i4.x
              + (u4.y + acc.y * invnorm) * i4.y
              + (u4.z + acc.z * invnorm) * i4.z
              + (u4.w + acc.w * invnorm) * i4.w;

    // Reduce 16 chunks (both halves hold identical values post-fold).
    #pragma unroll
    for (int off = 8; off > 0; off >>= 1)
        dot += __shfl_down_sync(0xffffffffu, dot, off, 16);

    if (lane == 0)
        out[b] = dot + ub + ib + gb;
}

extern "C" void kernel_launch(void* const* d_in, const int* in_sizes, int n_in,
                              void* d_out, int out_size) {
    const int*    user_ids      = (const int*)d_in[0];
    const int*    item_ids      = (const int*)d_in[1];
    const int*    offsets       = (const int*)d_in[2];
    const int*    flat_implicit = (const int*)d_in[3];
    const float4* user_emb4     = (const float4*)d_in[4];
    const float4* item_emb4     = (const float4*)d_in[5];
    const float4* imp_emb4      = (const float4*)d_in[6];
    const float*  user_bias     = (const float*)d_in[7];
    const float*  item_bias     = (const float*)d_in[8];
    const float*  global_bias   = (const float*)d_in[9];
    float*        out           = (float*)d_out;

    const int B = in_sizes[0];          // 16384
    const int N = in_sizes[3];          // 819200

    svdpp_kernel<<<(B + 3) / 4, 128>>>(user_ids, item_ids, offsets, flat_implicit,
                                       user_emb4, item_emb4, imp_emb4,
                                       user_bias, item_bias, global_bias,
                                       out, B, N);
}

// round 17
// speedup vs baseline: 1.7672x; 1.1299x over previous
#include <cuda_runtime.h>

// CTA per row, 64 thr = 4 slots x 16 lanes. Indices for the whole segment are
// staged to smem first (coalesced), so the row-gather loop has NO global
// idx->row dependency chain: row loads pipeline across iterations freely.

#define TILE_IDX 512

__global__ __launch_bounds__(64)
void svdpp_kernel(const int* __restrict__ user_ids,
                  const int* __restrict__ item_ids,
                  const int* __restrict__ offsets,
                  const int* __restrict__ flat_implicit,
                  const float4* __restrict__ user_emb4,
                  const float4* __restrict__ item_emb4,
                  const float4* __restrict__ imp_emb4,
                  const float* __restrict__ user_bias,
                  const float* __restrict__ item_bias,
                  const float* __restrict__ global_bias,
                  float* __restrict__ out,
                  int B, int N) {
    const int b    = blockIdx.x;
    const int tid  = threadIdx.x;
    const int lane = tid & 15;          // float4 chunk of the 256B row
    const int slot = tid >> 4;          // item slot 0..3

    __shared__ int    sidx[TILE_IDX];
    __shared__ float4 sred[16];

    const int start = __ldg(&offsets[b]);
    const int end   = (b + 1 < B) ? __ldg(&offsets[b + 1]) : N;
    const int len   = end - start;

    // Epilogue operands issued early; latency hides under the gather.
    const int u  = __ldg(&user_ids[b]);
    const int it = __ldg(&item_ids[b]);
    const float4 u4 = __ldg(&user_emb4[(size_t)u * 16 + lane]);
    const float4 i4 = __ldg(&item_emb4[(size_t)it * 16 + lane]);
    const float  ub = __ldg(&user_bias[u]);
    const float  ib = __ldg(&item_bias[it]);
    const float  gb = __ldg(&global_bias[0]);

    float4 acc = make_float4(0.f, 0.f, 0.f, 0.f);

    for (int tbase = start; tbase < end; tbase += TILE_IDX) {
        const int tlen = min(TILE_IDX, end - tbase);

        // Phase 0: coalesced index staging (1 LDG.32 per 64 indices).
        for (int k = tid; k < tlen; k += 64)
            sidx[k] = __ldg(&flat_implicit[tbase + k]);
        __syncthreads();

        // Phase 1: chain-free gather. Addresses come from smem; row loads
        // pipeline across iterations up to scoreboard depth.
        int k = slot;
        for (; k + 12 < tlen; k += 16) {
            const int i0 = sidx[k];
            const int i1 = sidx[k + 4];
            const int i2 = sidx[k + 8];
            const int i3 = sidx[k + 12];
            const float4 a0 = __ldg(&imp_emb4[(size_t)i0 * 16 + lane]);
            const float4 a1 = __ldg(&imp_emb4[(size_t)i1 * 16 + lane]);
            const float4 a2 = __ldg(&imp_emb4[(size_t)i2 * 16 + lane]);
            const float4 a3 = __ldg(&imp_emb4[(size_t)i3 * 16 + lane]);
            acc.x += (a0.x + a1.x) + (a2.x + a3.x);
            acc.y += (a0.y + a1.y) + (a2.y + a3.y);
            acc.z += (a0.z + a1.z) + (a2.z + a3.z);
            acc.w += (a0.w + a1.w) + (a2.w + a3.w);
        }
        for (; k < tlen; k += 4) {
            const float4 a = __ldg(&imp_emb4[(size_t)sidx[k] * 16 + lane]);
            acc.x += a.x; acc.y += a.y; acc.z += a.z; acc.w += a.w;
        }
        __syncthreads();   // protect sidx for next tile
    }

    // Combine slots 0/1 (warp 0) and 2/3 (warp 1).
    acc.x += __shfl_xor_sync(0xffffffffu, acc.x, 16);
    acc.y += __shfl_xor_sync(0xffffffffu, acc.y, 16);
    acc.z += __shfl_xor_sync(0xffffffffu, acc.z, 16);
    acc.w += __shfl_xor_sync(0xffffffffu, acc.w, 16);

    if (tid >= 32 && tid < 48) sred[lane] = acc;   // warp 1, lanes 0-15
    __syncthreads();

    if (tid < 16) {
        const float4 o = sred[tid];
        acc.x += o.x; acc.y += o.y; acc.z += o.z; acc.w += o.w;

        const float invnorm = (len > 0) ? rsqrtf((float)len) : 1.0f;

        float dot = (u4.x + acc.x * invnorm) * i4.x
                  + (u4.y + acc.y * invnorm) * i4.y
                  + (u4.z + acc.z * invnorm) * i4.z
                  + (u4.w + acc.w * invnorm) * i4.w;

        #pragma unroll
        for (int off = 8; off > 0; off >>= 1)
            dot += __shfl_down_sync(0x0000ffffu, dot, off);

        if (tid == 0)
            out[b] = dot + ub + ib + gb;
    }
}

extern "C" void kernel_launch(void* const* d_in, const int* in_sizes, int n_in,
                              void* d_out, int out_size) {
    const int*    user_ids      = (const int*)d_in[0];
    const int*    item_ids      = (const int*)d_in[1];
    const int*    offsets       = (const int*)d_in[2];
    const int*    flat_implicit = (const int*)d_in[3];
    const float4* user_emb4     = (const float4*)d_in[4];
    const float4* item_emb4     = (const float4*)d_in[5];
    const float4* imp_emb4      = (const float4*)d_in[6];
    const float*  user_bias     = (const float*)d_in[7];
    const float*  item_bias     = (const float*)d_in[8];
    const float*  global_bias   = (const float*)d_in[9];
    float*        out           = (float*)d_out;

    const int B = in_sizes[0];          // 16384
    const int N = in_sizes[3];          // 819200

    svdpp_kernel<<<B, 64>>>(user_ids, item_ids, offsets, flat_implicit,
                            user_emb4, item_emb4, imp_emb4,
                            user_bias, item_bias, global_bias,
                            out, B, N);
}